// round 4
// baseline (speedup 1.0000x reference)
#include <cuda_runtime.h>

#define NB 8
#define NTX 128
#define NTY 128
#define ND 512
#define NH 512

// Scratch (allocation-free rule: __device__ globals)
__device__ float g_WcT[NB * NH * NTX];            // [b][h][tx]
__device__ float g_UxT[NB * NH * NTY];            // [b][h][ty]
__device__ float g_scores[NB * NTY * NTX];        // [b][ty][tx]

__device__ __forceinline__ float tanh_fast(float x) {
    float y;
    asm("tanh.approx.f32 %0, %1;" : "=f"(y) : "f"(x));
    return y;
}

// ---------------------------------------------------------------------------
// Kernel 1: OutT[b][h][t] = sum_d A[b][t][d] * W[d][h] + bias[h]
// (unchanged — measured at the fp32 FFMA roofline)
// ---------------------------------------------------------------------------
__global__ void __launch_bounds__(256)
bahdanau_gemm_t(const float* __restrict__ Ctx, const float* __restrict__ X,
                const float* __restrict__ Wa, const float* __restrict__ bWa,
                const float* __restrict__ Ua, const float* __restrict__ bUa)
{
    const int which = blockIdx.z >> 3;       // 0: Wc, 1: Ux
    const int b     = blockIdx.z & 7;
    const float* A    = (which ? X  : Ctx) + b * NTX * ND;   // [128][512]
    const float* W    =  which ? Ua : Wa;                    // [512][512]
    const float* bias =  which ? bUa : bWa;
    float* OutT = (which ? g_UxT : g_WcT) + b * NH * NTX;    // [512][128]

    __shared__ float As[16][64 + 4];  // [k][t]
    __shared__ float Bs[16][64 + 4];  // [k][h]

    const int h0 = blockIdx.x * 64;
    const int t0 = blockIdx.y * 64;
    const int tx = threadIdx.x;       // -> t
    const int ty = threadIdx.y;       // -> h
    const int tid = ty * 16 + tx;

    float acc[4][4];
#pragma unroll
    for (int j = 0; j < 4; j++)
#pragma unroll
        for (int i = 0; i < 4; i++) acc[j][i] = 0.f;

    for (int k0 = 0; k0 < ND; k0 += 16) {
        {   // A tile: 64 t x 16 k
            int t  = tid >> 2;
            int kl = (tid & 3) * 4;
            float4 v = *reinterpret_cast<const float4*>(&A[(t0 + t) * ND + k0 + kl]);
            As[kl + 0][t] = v.x; As[kl + 1][t] = v.y;
            As[kl + 2][t] = v.z; As[kl + 3][t] = v.w;
        }
        {   // W tile: 16 k x 64 h
            int r = tid >> 4;
            int c = (tid & 15) * 4;
            float4 v = *reinterpret_cast<const float4*>(&W[(k0 + r) * NH + h0 + c]);
            Bs[r][c + 0] = v.x; Bs[r][c + 1] = v.y;
            Bs[r][c + 2] = v.z; Bs[r][c + 3] = v.w;
        }
        __syncthreads();
#pragma unroll
        for (int kk = 0; kk < 16; kk++) {
            float a[4], w[4];
#pragma unroll
            for (int i = 0; i < 4; i++) a[i] = As[kk][tx * 4 + i];
#pragma unroll
            for (int j = 0; j < 4; j++) w[j] = Bs[kk][ty * 4 + j];
#pragma unroll
            for (int j = 0; j < 4; j++)
#pragma unroll
                for (int i = 0; i < 4; i++) acc[j][i] += w[j] * a[i];
        }
        __syncthreads();
    }

#pragma unroll
    for (int j = 0; j < 4; j++) {
        int h = h0 + ty * 4 + j;
        float bv = bias[h];
        float4 v = make_float4(acc[j][0] + bv, acc[j][1] + bv,
                               acc[j][2] + bv, acc[j][3] + bv);
        *reinterpret_cast<float4*>(&OutT[h * NTX + t0 + tx * 4]) = v;
    }
}

// ---------------------------------------------------------------------------
// Kernel 2: scores[b][ty][tx] = sum_h tanh(WcT[b][h][tx] + UxT[b][h][ty])*Va[h]
// Block = (b, ty-group of 8, tx-half of 64). 256 threads = 64 txi x 4 H-quarters.
// Per thread: 128 h x 8 tanh (ILP 8), depth-4 h prefetch of the WcT column.
// Grid = 8 * 16 * 2 = 256 blocks.
// ---------------------------------------------------------------------------
__global__ void __launch_bounds__(256)
bahdanau_scores(const float* __restrict__ Va, float* __restrict__ scores)
{
    const int b   = blockIdx.x >> 5;
    const int tyg = (blockIdx.x >> 1) & 15;
    const int txh = blockIdx.x & 1;
    const int ty0 = tyg * 8;
    const int tx0 = txh * 64;

    __shared__ __align__(16) float ux_s[NH * 8];        // 16 KB: [h][j]
    __shared__ __align__(16) float va_s[NH];            //  2 KB
    __shared__ __align__(16) float part[4][8][64];      //  8 KB

    const int tid = threadIdx.x;
    const int txi = tid & 63;
    const int q   = tid >> 6;

    // Stage Ux (8 ty rows, all h) and Va
    for (int i = tid; i < NH * 8; i += 256) {
        int h = i >> 3, j = i & 7;
        ux_s[i] = g_UxT[(b * NH + h) * NTY + ty0 + j];
    }
    for (int i = tid; i < NH; i += 256) va_s[i] = Va[i];
    __syncthreads();

    float s[8];
#pragma unroll
    for (int j = 0; j < 8; j++) s[j] = 0.f;

    const float* wp = g_WcT + (b * NH + q * 128) * NTX + tx0 + txi;

    float wr[4];
#pragma unroll
    for (int i = 0; i < 4; i++) wr[i] = __ldg(wp + i * NTX);

#pragma unroll 1
    for (int hh = 0; hh < 128; hh += 4) {
        float wn[4];
        const bool more = (hh + 4) < 128;
#pragma unroll
        for (int i = 0; i < 4; i++)
            wn[i] = more ? __ldg(wp + (hh + 4 + i) * NTX) : 0.f;

#pragma unroll
        for (int i = 0; i < 4; i++) {
            const int h = q * 128 + hh + i;
            const float v = va_s[h];
            const float w = wr[i];
            float4 u0 = *reinterpret_cast<const float4*>(&ux_s[h * 8]);
            float4 u1 = *reinterpret_cast<const float4*>(&ux_s[h * 8 + 4]);
            s[0] += tanh_fast(w + u0.x) * v;
            s[1] += tanh_fast(w + u0.y) * v;
            s[2] += tanh_fast(w + u0.z) * v;
            s[3] += tanh_fast(w + u0.w) * v;
            s[4] += tanh_fast(w + u1.x) * v;
            s[5] += tanh_fast(w + u1.y) * v;
            s[6] += tanh_fast(w + u1.z) * v;
            s[7] += tanh_fast(w + u1.w) * v;
        }
#pragma unroll
        for (int i = 0; i < 4; i++) wr[i] = wn[i];
    }

#pragma unroll
    for (int j = 0; j < 8; j++) part[q][j][txi] = s[j];
    __syncthreads();

    // Reduce quarters, write final scores. 256 threads cover 512 outputs.
#pragma unroll
    for (int r = 0; r < 2; r++) {
        const int idx = tid + r * 256;          // 0..511
        const int j  = idx >> 6;
        const int ti = idx & 63;
        float v = part[0][j][ti] + part[1][j][ti] + part[2][j][ti] + part[3][j][ti];
        scores[(b * NTY + ty0 + j) * NTX + tx0 + ti] = v;
    }
}

// ---------------------------------------------------------------------------
// Kernel 3: softmax over tx + cv = attn @ context + LayerNorm + residual.
// Block = (b, ty-quad). 256 threads. Grid = 8 * 32 = 256.
// ---------------------------------------------------------------------------
__global__ void __launch_bounds__(256)
bahdanau_epilogue(const float* __restrict__ Ctx, const float* __restrict__ X,
                  const float* __restrict__ scores,
                  const float* __restrict__ gamma, const float* __restrict__ beta,
                  float* __restrict__ out)
{
    const int b   = blockIdx.x >> 5;
    const int ty0 = (blockIdx.x & 31) * 4;

    __shared__ __align__(16) float attn_s[4][NTX];   // 2 KB
    __shared__ __align__(16) float cv_s[4][ND];      // 8 KB

    const int tid = threadIdx.x;

    // Softmax: warp j (j<4) handles ty row ty0+j
    if (tid < 128) {
        const int j = tid >> 5, lane = tid & 31;
        const float* srow = scores + ((size_t)b * NTY + ty0 + j) * NTX;
        float vals[4];
        float mx = -1e30f;
#pragma unroll
        for (int i = 0; i < 4; i++) {
            vals[i] = srow[lane + i * 32];
            mx = fmaxf(mx, vals[i]);
        }
#pragma unroll
        for (int off = 16; off; off >>= 1)
            mx = fmaxf(mx, __shfl_xor_sync(0xffffffffu, mx, off));
        float sum = 0.f;
#pragma unroll
        for (int i = 0; i < 4; i++) {
            vals[i] = __expf(vals[i] - mx);
            sum += vals[i];
        }
#pragma unroll
        for (int off = 16; off; off >>= 1)
            sum += __shfl_xor_sync(0xffffffffu, sum, off);
        float inv = __frcp_rn(sum);
#pragma unroll
        for (int i = 0; i < 4; i++)
            attn_s[j][lane + i * 32] = vals[i] * inv;
    }
    __syncthreads();

    // cv[j][d] = sum_tx attn[j][tx] * context[b][tx][d]; thread owns 2 d's.
    {
        const int d0 = tid * 2;
        float acc[4][2];
#pragma unroll
        for (int j = 0; j < 4; j++) { acc[j][0] = 0.f; acc[j][1] = 0.f; }
        const float* cbase = Ctx + (size_t)b * NTX * ND + d0;
#pragma unroll 4
        for (int t = 0; t < NTX; t++) {
            float2 c = *reinterpret_cast<const float2*>(cbase + (size_t)t * ND);
#pragma unroll
            for (int j = 0; j < 4; j++) {
                float a = attn_s[j][t];
                acc[j][0] += a * c.x;
                acc[j][1] += a * c.y;
            }
        }
#pragma unroll
        for (int j = 0; j < 4; j++) {
            cv_s[j][d0]     = acc[j][0];
            cv_s[j][d0 + 1] = acc[j][1];
        }
    }
    __syncthreads();

    // LayerNorm + residual: warp j (j<4) handles row j
    if (tid < 128) {
        const int j = tid >> 5, lane = tid & 31;
        float vals[16];
        float sum = 0.f;
#pragma unroll
        for (int i = 0; i < 16; i++) {
            vals[i] = cv_s[j][i * 32 + lane];
            sum += vals[i];
        }
#pragma unroll
        for (int off = 16; off; off >>= 1)
            sum += __shfl_xor_sync(0xffffffffu, sum, off);
        const float mean = sum * (1.0f / ND);
        float vsum = 0.f;
#pragma unroll
        for (int i = 0; i < 16; i++) {
            float dlt = vals[i] - mean;
            vsum += dlt * dlt;
        }
#pragma unroll
        for (int off = 16; off; off >>= 1)
            vsum += __shfl_xor_sync(0xffffffffu, vsum, off);
        const float scale = rsqrtf(vsum * (1.0f / ND) + 1e-3f);

        const int ty = ty0 + j;
        const float* xr = X + ((size_t)b * NTY + ty) * ND;
        float* orow = out + ((size_t)b * NTY + ty) * ND;
#pragma unroll
        for (int i = 0; i < 16; i++) {
            int d = i * 32 + lane;
            orow[d] = (vals[i] - mean) * scale * gamma[d] + beta[d] + xr[d];
        }
    }
}

// ---------------------------------------------------------------------------
extern "C" void kernel_launch(void* const* d_in, const int* in_sizes, int n_in,
                              void* d_out, int out_size)
{
    const float* ctx   = (const float*)d_in[0];
    const float* x     = (const float*)d_in[1];
    const float* Wa    = (const float*)d_in[2];
    const float* bWa   = (const float*)d_in[3];
    const float* Ua    = (const float*)d_in[4];
    const float* bUa   = (const float*)d_in[5];
    const float* Va    = (const float*)d_in[6];
    // d_in[7] = bVa: scalar added to scores; cancels exactly in softmax.
    const float* gamma = (const float*)d_in[8];
    const float* beta  = (const float*)d_in[9];
    float* out = (float*)d_out;

    float* scores;
    cudaGetSymbolAddress((void**)&scores, g_scores);

    dim3 g1(NH / 64, NTX / 64, NB * 2);   // (8, 2, 16)
    dim3 b1(16, 16);
    bahdanau_gemm_t<<<g1, b1>>>(ctx, x, Wa, bWa, Ua, bUa);

    bahdanau_scores<<<NB * 16 * 2, 256>>>(Va, scores);

    bahdanau_epilogue<<<NB * 32, 256>>>(ctx, x, scores, gamma, beta, out);
}

// round 5
// speedup vs baseline: 1.4165x; 1.4165x over previous
#include <cuda_runtime.h>
#include <cstdint>

#define NB 8
#define NTX 128
#define NTY 128
#define ND 512
#define NH 512
#define TYB 8

// Scratch (allocation-free rule: __device__ globals)
__device__ float g_WcT[NB * NH * NTX];   // [b][h][tx]
__device__ float g_UxT[NB * NH * NTY];   // [b][h][ty]

__device__ __forceinline__ float tanh_fast(float x) {
    float y;
    asm("tanh.approx.f32 %0, %1;" : "=f"(y) : "f"(x));
    return y;
}

__device__ __forceinline__ uint32_t f2tf32(float x) {
    uint32_t r;
    asm("cvt.rna.tf32.f32 %0, %1;" : "=r"(r) : "f"(x));
    return r;
}

__device__ __forceinline__ void mma_tf32(float d[4], const uint32_t a[4],
                                         const uint32_t b[2]) {
    asm volatile(
        "mma.sync.aligned.m16n8k8.row.col.f32.tf32.tf32.f32 "
        "{%0,%1,%2,%3}, {%4,%5,%6,%7}, {%8,%9}, {%0,%1,%2,%3};"
        : "+f"(d[0]), "+f"(d[1]), "+f"(d[2]), "+f"(d[3])
        : "r"(a[0]), "r"(a[1]), "r"(a[2]), "r"(a[3]), "r"(b[0]), "r"(b[1]));
}

// ---------------------------------------------------------------------------
// Kernel 1 (tensor core): OutT[b][h][t] = sum_d A[b][t][d]*W[d][h] + bias[h]
// tf32 mma.sync m16n8k8. Block = 128 thr (4 warps, 2x2), tile 64(t) x 64(h),
// K chunks of 32, register-prefetch of the next chunk overlapping compute.
// Grid (8 h-tiles, 2 t-tiles, 16 b*which).
// ---------------------------------------------------------------------------
__global__ void __launch_bounds__(128)
bahdanau_gemm_tc(const float* __restrict__ Ctx, const float* __restrict__ X,
                 const float* __restrict__ Wa, const float* __restrict__ bWa,
                 const float* __restrict__ Ua, const float* __restrict__ bUa)
{
    const int which = blockIdx.z >> 3;       // 0: Wc, 1: Ux
    const int b     = blockIdx.z & 7;
    const float* A    = (which ? X  : Ctx) + b * NTX * ND;   // [128][512]
    const float* W    =  which ? Ua : Wa;                    // [512][512]
    const float* bias =  which ? bUa : bWa;
    float* OutT = (which ? g_UxT : g_WcT) + b * NH * NTX;    // [512][128]

    const int h0 = blockIdx.x * 64;
    const int t0 = blockIdx.y * 64;

    __shared__ __align__(16) float pool[4480];               // 17.5 KB
    float (*As)[36]   = reinterpret_cast<float(*)[36]>(pool);          // [64][36]
    float (*Bs)[68]   = reinterpret_cast<float(*)[68]>(pool + 2304);   // [32][68]
    float (*Sout)[68] = reinterpret_cast<float(*)[68]>(pool);          // [64][68]

    const int tid  = threadIdx.x;
    const int warp = tid >> 5, lane = tid & 31;
    const int wm = warp >> 1, wn = warp & 1;    // 2x2 warp grid
    const int gid = lane >> 2, tq = lane & 3;

    // loader indexing
    const int arow = tid >> 1, ahalf = tid & 1;  // A: 64 rows x (2x16 cols)
    const int brow = tid >> 2, bq = tid & 3;     // B: 32 rows x (4x16 cols)

    const float* Abase = A + (t0 + arow) * ND + ahalf * 16;
    const float* Bbase = W + brow * NH + h0 + bq * 16;

    float4 pa[4], pb[4];
#pragma unroll
    for (int i = 0; i < 4; i++) pa[i] = *(const float4*)(Abase + i * 4);
#pragma unroll
    for (int i = 0; i < 4; i++) pb[i] = *(const float4*)(Bbase + i * 4);

    float acc[2][4][4];
#pragma unroll
    for (int mt = 0; mt < 2; mt++)
#pragma unroll
        for (int nt = 0; nt < 4; nt++)
#pragma unroll
            for (int r = 0; r < 4; r++) acc[mt][nt][r] = 0.f;

#pragma unroll 1
    for (int kc = 0; kc < 16; kc++) {
        __syncthreads();   // previous iteration's smem reads complete
#pragma unroll
        for (int i = 0; i < 4; i++) {
            float4 v = pa[i];
            uint4 u = make_uint4(f2tf32(v.x), f2tf32(v.y), f2tf32(v.z), f2tf32(v.w));
            *reinterpret_cast<uint4*>(&As[arow][ahalf * 16 + i * 4]) = u;
        }
#pragma unroll
        for (int i = 0; i < 4; i++) {
            float4 v = pb[i];
            uint4 u = make_uint4(f2tf32(v.x), f2tf32(v.y), f2tf32(v.z), f2tf32(v.w));
            *reinterpret_cast<uint4*>(&Bs[brow][bq * 16 + i * 4]) = u;
        }
        __syncthreads();

        if (kc < 15) {  // prefetch next chunk (overlaps with mma below)
            const float* an = Abase + (kc + 1) * 32;
            const float* bn = Bbase + (size_t)(kc + 1) * 32 * NH;
#pragma unroll
            for (int i = 0; i < 4; i++) pa[i] = *(const float4*)(an + i * 4);
#pragma unroll
            for (int i = 0; i < 4; i++) pb[i] = *(const float4*)(bn + i * 4);
        }

#pragma unroll
        for (int ks = 0; ks < 4; ks++) {
            const int kb = ks * 8;
            uint32_t af[2][4], bf[4][2];
#pragma unroll
            for (int mt = 0; mt < 2; mt++) {
                const int r = wm * 32 + mt * 16 + gid;
                af[mt][0] = __float_as_uint(As[r    ][kb + tq]);
                af[mt][1] = __float_as_uint(As[r + 8][kb + tq]);
                af[mt][2] = __float_as_uint(As[r    ][kb + tq + 4]);
                af[mt][3] = __float_as_uint(As[r + 8][kb + tq + 4]);
            }
#pragma unroll
            for (int nt = 0; nt < 4; nt++) {
                const int c = wn * 32 + nt * 8 + gid;
                bf[nt][0] = __float_as_uint(Bs[kb + tq    ][c]);
                bf[nt][1] = __float_as_uint(Bs[kb + tq + 4][c]);
            }
#pragma unroll
            for (int mt = 0; mt < 2; mt++)
#pragma unroll
                for (int nt = 0; nt < 4; nt++)
                    mma_tf32(acc[mt][nt], af[mt], bf[nt]);
        }
    }
    __syncthreads();

    // Transpose via smem: Sout[n(h)][m(t)]
#pragma unroll
    for (int mt = 0; mt < 2; mt++)
#pragma unroll
        for (int nt = 0; nt < 4; nt++) {
            const int n = wn * 32 + nt * 8 + 2 * tq;
            const int m = wm * 32 + mt * 16 + gid;
            Sout[n    ][m    ] = acc[mt][nt][0];
            Sout[n + 1][m    ] = acc[mt][nt][1];
            Sout[n    ][m + 8] = acc[mt][nt][2];
            Sout[n + 1][m + 8] = acc[mt][nt][3];
        }
    __syncthreads();

    // Vectorized store with bias: row = h index
    {
        const int row = tid >> 1, half = tid & 1;
        const float bv = __ldg(&bias[h0 + row]);
        float* orow = OutT + (size_t)(h0 + row) * NTX + t0 + half * 32;
#pragma unroll
        for (int i = 0; i < 8; i++) {
            float4 v = *reinterpret_cast<const float4*>(&Sout[row][half * 32 + i * 4]);
            v.x += bv; v.y += bv; v.z += bv; v.w += bv;
            *reinterpret_cast<float4*>(orow + i * 4) = v;
        }
    }
}

// ---------------------------------------------------------------------------
// Kernel 2 (R2 best-measured): fused scores + softmax + cv + LayerNorm +
// residual. Block = (b, 8 ty rows), 512 threads, grid 128.
// ---------------------------------------------------------------------------
__global__ void __launch_bounds__(512)
bahdanau_attn(const float* __restrict__ Ctx, const float* __restrict__ X,
              const float* __restrict__ Va, const float* __restrict__ gamma,
              const float* __restrict__ beta, float* __restrict__ out)
{
    const int b   = blockIdx.x >> 4;
    const int ty0 = (blockIdx.x & 15) * TYB;

    __shared__ __align__(16) float va_s[NH];        //  2 KB
    __shared__ __align__(16) float pool[8192];      // 32 KB (overlaid)
    __shared__ __align__(16) float attn_s[TYB][NTX];//  4 KB

    const int tid = threadIdx.x;

    for (int i = tid; i < NH * TYB; i += 512) {
        int h = i >> 3, j = i & 7;
        pool[i] = g_UxT[(b * NH + h) * NTY + ty0 + j];  // ux_s[h][j]
    }
    if (tid < NH) va_s[tid] = Va[tid];
    __syncthreads();

    // ---- Phase 1: s[j] = sum_h tanh(Wc[tx,h] + Ux[ty0+j,h]) * Va[h]
    {
        const int txi = tid & 127;
        const int q   = tid >> 7;
        float s[TYB];
#pragma unroll
        for (int j = 0; j < TYB; j++) s[j] = 0.f;

        const float* wp = g_WcT + (b * NH + q * 128) * NTX + txi;

        float wr[4];
#pragma unroll
        for (int i = 0; i < 4; i++) wr[i] = __ldg(wp + i * NTX);

#pragma unroll 1
        for (int hh = 0; hh < 128; hh += 4) {
            float wn[4];
            const bool more = (hh + 4) < 128;
#pragma unroll
            for (int i = 0; i < 4; i++)
                wn[i] = more ? __ldg(wp + (hh + 4 + i) * NTX) : 0.f;

#pragma unroll
            for (int i = 0; i < 4; i++) {
                const int h = q * 128 + hh + i;
                const float v = va_s[h];
                const float w = wr[i];
                float4 u0 = *reinterpret_cast<const float4*>(&pool[h * 8]);
                float4 u1 = *reinterpret_cast<const float4*>(&pool[h * 8 + 4]);
                s[0] += tanh_fast(w + u0.x) * v;
                s[1] += tanh_fast(w + u0.y) * v;
                s[2] += tanh_fast(w + u0.z) * v;
                s[3] += tanh_fast(w + u0.w) * v;
                s[4] += tanh_fast(w + u1.x) * v;
                s[5] += tanh_fast(w + u1.y) * v;
                s[6] += tanh_fast(w + u1.z) * v;
                s[7] += tanh_fast(w + u1.w) * v;
            }
#pragma unroll
            for (int i = 0; i < 4; i++) wr[i] = wn[i];
        }
        __syncthreads();
#pragma unroll
        for (int j = 0; j < TYB; j++)
            pool[4096 + q * 1024 + j * 128 + txi] = s[j];
    }
    __syncthreads();

    // ---- Phase 2: softmax over tx per ty row; warp j (j<8) handles row j.
    if (tid < 256) {
        const int j = tid >> 5, lane = tid & 31;
        float vals[4];
        float mx = -1e30f;
#pragma unroll
        for (int i = 0; i < 4; i++) {
            int t = lane + i * 32;
            vals[i] = pool[4096 + 0 * 1024 + j * 128 + t]
                    + pool[4096 + 1 * 1024 + j * 128 + t]
                    + pool[4096 + 2 * 1024 + j * 128 + t]
                    + pool[4096 + 3 * 1024 + j * 128 + t];
            mx = fmaxf(mx, vals[i]);
        }
#pragma unroll
        for (int off = 16; off; off >>= 1)
            mx = fmaxf(mx, __shfl_xor_sync(0xffffffffu, mx, off));
        float sum = 0.f;
#pragma unroll
        for (int i = 0; i < 4; i++) {
            vals[i] = __expf(vals[i] - mx);
            sum += vals[i];
        }
#pragma unroll
        for (int off = 16; off; off >>= 1)
            sum += __shfl_xor_sync(0xffffffffu, sum, off);
        float inv = __frcp_rn(sum);
#pragma unroll
        for (int i = 0; i < 4; i++)
            attn_s[j][lane + i * 32] = vals[i] * inv;
    }
    __syncthreads();

    // ---- Phase 3: cv[j][d] = sum_tx attn[j][tx] * context[b][tx][d]
    {
        const int g  = tid >> 8;
        const int l  = tid & 255;
        const int d0 = l * 2;
        float acc[TYB][2];
#pragma unroll
        for (int j = 0; j < TYB; j++) { acc[j][0] = 0.f; acc[j][1] = 0.f; }
        const float* cbase = Ctx + (size_t)b * NTX * ND + (size_t)(g * 64) * ND + d0;
#pragma unroll 4
        for (int t = 0; t < 64; t++) {
            float2 c = *reinterpret_cast<const float2*>(cbase + (size_t)t * ND);
            const int tt = g * 64 + t;
#pragma unroll
            for (int j = 0; j < TYB; j++) {
                float a = attn_s[j][tt];
                acc[j][0] += a * c.x;
                acc[j][1] += a * c.y;
            }
        }
#pragma unroll
        for (int j = 0; j < TYB; j++) {
            pool[g * 4096 + j * 512 + d0]     = acc[j][0];
            pool[g * 4096 + j * 512 + d0 + 1] = acc[j][1];
        }
    }
    __syncthreads();

    // ---- Phase 4: LayerNorm + residual. Warp j (j<8) handles row j.
    if (tid < 256) {
        const int j = tid >> 5, lane = tid & 31;
        float vals[16];
        float sum = 0.f;
#pragma unroll
        for (int i = 0; i < 16; i++) {
            int d = i * 32 + lane;
            vals[i] = pool[j * 512 + d] + pool[4096 + j * 512 + d];
            sum += vals[i];
        }
#pragma unroll
        for (int off = 16; off; off >>= 1)
            sum += __shfl_xor_sync(0xffffffffu, sum, off);
        const float mean = sum * (1.0f / ND);
        float vsum = 0.f;
#pragma unroll
        for (int i = 0; i < 16; i++) {
            float dlt = vals[i] - mean;
            vsum += dlt * dlt;
        }
#pragma unroll
        for (int off = 16; off; off >>= 1)
            vsum += __shfl_xor_sync(0xffffffffu, vsum, off);
        const float scale = rsqrtf(vsum * (1.0f / ND) + 1e-3f);

        const int ty = ty0 + j;
        const float* xr = X + ((size_t)b * NTY + ty) * ND;
        float* orow = out + ((size_t)b * NTY + ty) * ND;
#pragma unroll
        for (int i = 0; i < 16; i++) {
            int d = i * 32 + lane;
            orow[d] = (vals[i] - mean) * scale * gamma[d] + beta[d] + xr[d];
        }
    }
}

// ---------------------------------------------------------------------------
extern "C" void kernel_launch(void* const* d_in, const int* in_sizes, int n_in,
                              void* d_out, int out_size)
{
    const float* ctx   = (const float*)d_in[0];
    const float* x     = (const float*)d_in[1];
    const float* Wa    = (const float*)d_in[2];
    const float* bWa   = (const float*)d_in[3];
    const float* Ua    = (const float*)d_in[4];
    const float* bUa   = (const float*)d_in[5];
    const float* Va    = (const float*)d_in[6];
    // d_in[7] = bVa: scalar added to scores; cancels exactly in softmax.
    const float* gamma = (const float*)d_in[8];
    const float* beta  = (const float*)d_in[9];
    float* out = (float*)d_out;

    dim3 g1(NH / 64, NTX / 64, NB * 2);   // (8, 2, 16)
    bahdanau_gemm_tc<<<g1, 128>>>(ctx, x, Wa, bWa, Ua, bUa);

    bahdanau_attn<<<NB * (NTY / TYB), 512>>>(ctx, x, Va, gamma, beta, out);
}

// round 6
// speedup vs baseline: 1.4241x; 1.0054x over previous
#include <cuda_runtime.h>
#include <cuda_fp16.h>
#include <cstdint>

#define NB 8
#define NTX 128
#define NTY 128
#define ND 512
#define NH 512
#define TYB 8

// Scratch (allocation-free rule: __device__ globals)
__device__ float g_WcT[NB * NH * NTX];   // [b][h][tx]
__device__ float g_UxT[NB * NH * NTY];   // [b][h][ty]

__device__ __forceinline__ uint32_t f2tf32(float x) {
    uint32_t r;
    asm("cvt.rna.tf32.f32 %0, %1;" : "=r"(r) : "f"(x));
    return r;
}

__device__ __forceinline__ void mma_tf32(float d[4], const uint32_t a[4],
                                         const uint32_t b[2]) {
    asm volatile(
        "mma.sync.aligned.m16n8k8.row.col.f32.tf32.tf32.f32 "
        "{%0,%1,%2,%3}, {%4,%5,%6,%7}, {%8,%9}, {%0,%1,%2,%3};"
        : "+f"(d[0]), "+f"(d[1]), "+f"(d[2]), "+f"(d[3])
        : "r"(a[0]), "r"(a[1]), "r"(a[2]), "r"(a[3]), "r"(b[0]), "r"(b[1]));
}

// tanh of two packed f16 values; inputs given as two f32, result two f32.
__device__ __forceinline__ float2 tanh2_f16(float lo, float hi) {
    uint32_t p, t;
    asm("cvt.rn.f16x2.f32 %0, %1, %2;" : "=r"(p) : "f"(hi), "f"(lo));
    asm("tanh.approx.f16x2 %0, %1;" : "=r"(t) : "r"(p));
    __half2 h2 = *reinterpret_cast<__half2*>(&t);
    return __half22float2(h2);   // .x = lo lane, .y = hi lane
}

// ---------------------------------------------------------------------------
// Kernel 1 (tensor core, unchanged from R5): OutT = A @ W + bias, transposed
// ---------------------------------------------------------------------------
__global__ void __launch_bounds__(128)
bahdanau_gemm_tc(const float* __restrict__ Ctx, const float* __restrict__ X,
                 const float* __restrict__ Wa, const float* __restrict__ bWa,
                 const float* __restrict__ Ua, const float* __restrict__ bUa)
{
    const int which = blockIdx.z >> 3;       // 0: Wc, 1: Ux
    const int b     = blockIdx.z & 7;
    const float* A    = (which ? X  : Ctx) + b * NTX * ND;   // [128][512]
    const float* W    =  which ? Ua : Wa;                    // [512][512]
    const float* bias =  which ? bUa : bWa;
    float* OutT = (which ? g_UxT : g_WcT) + b * NH * NTX;    // [512][128]

    const int h0 = blockIdx.x * 64;
    const int t0 = blockIdx.y * 64;

    __shared__ __align__(16) float pool[4480];               // 17.5 KB
    float (*As)[36]   = reinterpret_cast<float(*)[36]>(pool);          // [64][36]
    float (*Bs)[68]   = reinterpret_cast<float(*)[68]>(pool + 2304);   // [32][68]
    float (*Sout)[68] = reinterpret_cast<float(*)[68]>(pool);          // [64][68]

    const int tid  = threadIdx.x;
    const int warp = tid >> 5, lane = tid & 31;
    const int wm = warp >> 1, wn = warp & 1;    // 2x2 warp grid
    const int gid = lane >> 2, tq = lane & 3;

    const int arow = tid >> 1, ahalf = tid & 1;  // A: 64 rows x (2x16 cols)
    const int brow = tid >> 2, bq = tid & 3;     // B: 32 rows x (4x16 cols)

    const float* Abase = A + (t0 + arow) * ND + ahalf * 16;
    const float* Bbase = W + brow * NH + h0 + bq * 16;

    float4 pa[4], pb[4];
#pragma unroll
    for (int i = 0; i < 4; i++) pa[i] = *(const float4*)(Abase + i * 4);
#pragma unroll
    for (int i = 0; i < 4; i++) pb[i] = *(const float4*)(Bbase + i * 4);

    float acc[2][4][4];
#pragma unroll
    for (int mt = 0; mt < 2; mt++)
#pragma unroll
        for (int nt = 0; nt < 4; nt++)
#pragma unroll
            for (int r = 0; r < 4; r++) acc[mt][nt][r] = 0.f;

#pragma unroll 1
    for (int kc = 0; kc < 16; kc++) {
        __syncthreads();
#pragma unroll
        for (int i = 0; i < 4; i++) {
            float4 v = pa[i];
            uint4 u = make_uint4(f2tf32(v.x), f2tf32(v.y), f2tf32(v.z), f2tf32(v.w));
            *reinterpret_cast<uint4*>(&As[arow][ahalf * 16 + i * 4]) = u;
        }
#pragma unroll
        for (int i = 0; i < 4; i++) {
            float4 v = pb[i];
            uint4 u = make_uint4(f2tf32(v.x), f2tf32(v.y), f2tf32(v.z), f2tf32(v.w));
            *reinterpret_cast<uint4*>(&Bs[brow][bq * 16 + i * 4]) = u;
        }
        __syncthreads();

        if (kc < 15) {
            const float* an = Abase + (kc + 1) * 32;
            const float* bn = Bbase + (size_t)(kc + 1) * 32 * NH;
#pragma unroll
            for (int i = 0; i < 4; i++) pa[i] = *(const float4*)(an + i * 4);
#pragma unroll
            for (int i = 0; i < 4; i++) pb[i] = *(const float4*)(bn + i * 4);
        }

#pragma unroll
        for (int ks = 0; ks < 4; ks++) {
            const int kb = ks * 8;
            uint32_t af[2][4], bf[4][2];
#pragma unroll
            for (int mt = 0; mt < 2; mt++) {
                const int r = wm * 32 + mt * 16 + gid;
                af[mt][0] = __float_as_uint(As[r    ][kb + tq]);
                af[mt][1] = __float_as_uint(As[r + 8][kb + tq]);
                af[mt][2] = __float_as_uint(As[r    ][kb + tq + 4]);
                af[mt][3] = __float_as_uint(As[r + 8][kb + tq + 4]);
            }
#pragma unroll
            for (int nt = 0; nt < 4; nt++) {
                const int c = wn * 32 + nt * 8 + gid;
                bf[nt][0] = __float_as_uint(Bs[kb + tq    ][c]);
                bf[nt][1] = __float_as_uint(Bs[kb + tq + 4][c]);
            }
#pragma unroll
            for (int mt = 0; mt < 2; mt++)
#pragma unroll
                for (int nt = 0; nt < 4; nt++)
                    mma_tf32(acc[mt][nt], af[mt], bf[nt]);
        }
    }
    __syncthreads();

#pragma unroll
    for (int mt = 0; mt < 2; mt++)
#pragma unroll
        for (int nt = 0; nt < 4; nt++) {
            const int n = wn * 32 + nt * 8 + 2 * tq;
            const int m = wm * 32 + mt * 16 + gid;
            Sout[n    ][m    ] = acc[mt][nt][0];
            Sout[n + 1][m    ] = acc[mt][nt][1];
            Sout[n    ][m + 8] = acc[mt][nt][2];
            Sout[n + 1][m + 8] = acc[mt][nt][3];
        }
    __syncthreads();

    {
        const int row = tid >> 1, half = tid & 1;
        const float bv = __ldg(&bias[h0 + row]);
        float* orow = OutT + (size_t)(h0 + row) * NTX + t0 + half * 32;
#pragma unroll
        for (int i = 0; i < 8; i++) {
            float4 v = *reinterpret_cast<const float4*>(&Sout[row][half * 32 + i * 4]);
            v.x += bv; v.y += bv; v.z += bv; v.w += bv;
            *reinterpret_cast<float4*>(orow + i * 4) = v;
        }
    }
}

// ---------------------------------------------------------------------------
// Kernel 2: fused scores + softmax + cv + LayerNorm + residual.
// Phase 1 now uses tanh.approx.f16x2 (2 tanh per MUFU op).
// ---------------------------------------------------------------------------
__global__ void __launch_bounds__(512)
bahdanau_attn(const float* __restrict__ Ctx, const float* __restrict__ X,
              const float* __restrict__ Va, const float* __restrict__ gamma,
              const float* __restrict__ beta, float* __restrict__ out)
{
    const int b   = blockIdx.x >> 4;
    const int ty0 = (blockIdx.x & 15) * TYB;

    __shared__ __align__(16) float va_s[NH];        //  2 KB
    __shared__ __align__(16) float pool[8192];      // 32 KB (overlaid)
    __shared__ __align__(16) float attn_s[TYB][NTX];//  4 KB

    const int tid = threadIdx.x;

    for (int i = tid; i < NH * TYB; i += 512) {
        int h = i >> 3, j = i & 7;
        pool[i] = g_UxT[(b * NH + h) * NTY + ty0 + j];  // ux_s[h][j]
    }
    if (tid < NH) va_s[tid] = Va[tid];
    __syncthreads();

    // ---- Phase 1: s[j] = sum_h tanh(Wc[tx,h] + Ux[ty0+j,h]) * Va[h]
    {
        const int txi = tid & 127;
        const int q   = tid >> 7;
        float s[TYB];
#pragma unroll
        for (int j = 0; j < TYB; j++) s[j] = 0.f;

        const float* wp = g_WcT + (b * NH + q * 128) * NTX + txi;

        float wr[4];
#pragma unroll
        for (int i = 0; i < 4; i++) wr[i] = __ldg(wp + i * NTX);

#pragma unroll 1
        for (int hh = 0; hh < 128; hh += 4) {
            float wn[4];
            const bool more = (hh + 4) < 128;
#pragma unroll
            for (int i = 0; i < 4; i++)
                wn[i] = more ? __ldg(wp + (hh + 4 + i) * NTX) : 0.f;

#pragma unroll
            for (int i = 0; i < 4; i++) {
                const int h = q * 128 + hh + i;
                const float v = va_s[h];
                const float w = wr[i];
                float4 u0 = *reinterpret_cast<const float4*>(&pool[h * 8]);
                float4 u1 = *reinterpret_cast<const float4*>(&pool[h * 8 + 4]);
                float2 t0 = tanh2_f16(w + u0.x, w + u0.y);
                float2 t1 = tanh2_f16(w + u0.z, w + u0.w);
                float2 t2 = tanh2_f16(w + u1.x, w + u1.y);
                float2 t3 = tanh2_f16(w + u1.z, w + u1.w);
                s[0] += t0.x * v;  s[1] += t0.y * v;
                s[2] += t1.x * v;  s[3] += t1.y * v;
                s[4] += t2.x * v;  s[5] += t2.y * v;
                s[6] += t3.x * v;  s[7] += t3.y * v;
            }
#pragma unroll
            for (int i = 0; i < 4; i++) wr[i] = wn[i];
        }
        __syncthreads();
#pragma unroll
        for (int j = 0; j < TYB; j++)
            pool[4096 + q * 1024 + j * 128 + txi] = s[j];
    }
    __syncthreads();

    // ---- Phase 2: softmax over tx per ty row; warp j (j<8) handles row j.
    if (tid < 256) {
        const int j = tid >> 5, lane = tid & 31;
        float vals[4];
        float mx = -1e30f;
#pragma unroll
        for (int i = 0; i < 4; i++) {
            int t = lane + i * 32;
            vals[i] = pool[4096 + 0 * 1024 + j * 128 + t]
                    + pool[4096 + 1 * 1024 + j * 128 + t]
                    + pool[4096 + 2 * 1024 + j * 128 + t]
                    + pool[4096 + 3 * 1024 + j * 128 + t];
            mx = fmaxf(mx, vals[i]);
        }
#pragma unroll
        for (int off = 16; off; off >>= 1)
            mx = fmaxf(mx, __shfl_xor_sync(0xffffffffu, mx, off));
        float sum = 0.f;
#pragma unroll
        for (int i = 0; i < 4; i++) {
            vals[i] = __expf(vals[i] - mx);
            sum += vals[i];
        }
#pragma unroll
        for (int off = 16; off; off >>= 1)
            sum += __shfl_xor_sync(0xffffffffu, sum, off);
        float inv = __frcp_rn(sum);
#pragma unroll
        for (int i = 0; i < 4; i++)
            attn_s[j][lane + i * 32] = vals[i] * inv;
    }
    __syncthreads();

    // ---- Phase 3: cv[j][d] = sum_tx attn[j][tx] * context[b][tx][d]
    {
        const int g  = tid >> 8;
        const int l  = tid & 255;
        const int d0 = l * 2;
        float acc[TYB][2];
#pragma unroll
        for (int j = 0; j < TYB; j++) { acc[j][0] = 0.f; acc[j][1] = 0.f; }
        const float* cbase = Ctx + (size_t)b * NTX * ND + (size_t)(g * 64) * ND + d0;
#pragma unroll 4
        for (int t = 0; t < 64; t++) {
            float2 c = *reinterpret_cast<const float2*>(cbase + (size_t)t * ND);
            const int tt = g * 64 + t;
#pragma unroll
            for (int j = 0; j < TYB; j++) {
                float a = attn_s[j][tt];
                acc[j][0] += a * c.x;
                acc[j][1] += a * c.y;
            }
        }
#pragma unroll
        for (int j = 0; j < TYB; j++) {
            pool[g * 4096 + j * 512 + d0]     = acc[j][0];
            pool[g * 4096 + j * 512 + d0 + 1] = acc[j][1];
        }
    }
    __syncthreads();

    // ---- Phase 4: LayerNorm + residual. Warp j (j<8) handles row j.
    if (tid < 256) {
        const int j = tid >> 5, lane = tid & 31;
        float vals[16];
        float sum = 0.f;
#pragma unroll
        for (int i = 0; i < 16; i++) {
            int d = i * 32 + lane;
            vals[i] = pool[j * 512 + d] + pool[4096 + j * 512 + d];
            sum += vals[i];
        }
#pragma unroll
        for (int off = 16; off; off >>= 1)
            sum += __shfl_xor_sync(0xffffffffu, sum, off);
        const float mean = sum * (1.0f / ND);
        float vsum = 0.f;
#pragma unroll
        for (int i = 0; i < 16; i++) {
            float dlt = vals[i] - mean;
            vsum += dlt * dlt;
        }
#pragma unroll
        for (int off = 16; off; off >>= 1)
            vsum += __shfl_xor_sync(0xffffffffu, vsum, off);
        const float scale = rsqrtf(vsum * (1.0f / ND) + 1e-3f);

        const int ty = ty0 + j;
        const float* xr = X + ((size_t)b * NTY + ty) * ND;
        float* orow = out + ((size_t)b * NTY + ty) * ND;
#pragma unroll
        for (int i = 0; i < 16; i++) {
            int d = i * 32 + lane;
            orow[d] = (vals[i] - mean) * scale * gamma[d] + beta[d] + xr[d];
        }
    }
}

// ---------------------------------------------------------------------------
extern "C" void kernel_launch(void* const* d_in, const int* in_sizes, int n_in,
                              void* d_out, int out_size)
{
    const float* ctx   = (const float*)d_in[0];
    const float* x     = (const float*)d_in[1];
    const float* Wa    = (const float*)d_in[2];
    const float* bWa   = (const float*)d_in[3];
    const float* Ua    = (const float*)d_in[4];
    const float* bUa   = (const float*)d_in[5];
    const float* Va    = (const float*)d_in[6];
    // d_in[7] = bVa: scalar added to scores; cancels exactly in softmax.
    const float* gamma = (const float*)d_in[8];
    const float* beta  = (const float*)d_in[9];
    float* out = (float*)d_out;

    dim3 g1(NH / 64, NTX / 64, NB * 2);   // (8, 2, 16)
    bahdanau_gemm_tc<<<g1, 128>>>(ctx, x, Wa, bWa, Ua, bUa);

    bahdanau_attn<<<NB * (NTY / TYB), 512>>>(ctx, x, Va, gamma, beta, out);
}